// round 13
// baseline (speedup 1.0000x reference)
#include <cuda_runtime.h>
#include <cstdint>

#define NQ 4
#define NL 8

__device__ __align__(16) float g_T[112];   // 27 x (d0,d1,d2,pad)

__device__ __forceinline__ float2 cmul(float2 a, float2 b) {
    return make_float2(fmaf(a.x, b.x, -a.y * b.y), fmaf(a.x, b.y, a.y * b.x));
}
__device__ __forceinline__ float2 cfma(float2 a, float2 b, float2 acc) {
    acc.x = fmaf(a.x, b.x, fmaf(-a.y, b.y, acc.x));
    acc.y = fmaf(a.x, b.y, fmaf(a.y, b.x, acc.y));
    return acc;
}
__device__ __forceinline__ int cnot_map(int m, int c, int t) {
    int bc = 3 - c, bt = 3 - t;
    if ((m >> bc) & 1) m ^= (1 << bt);
    return m;
}

// One block, 256 threads. Log-depth product tree; early PDL trigger once g_T
// is written.
__global__ void vqc_setup(const float* __restrict__ w) {
    __shared__ float2 sGate[NL * NQ][4];
    __shared__ float2 sPA[NL][16];
    __shared__ float2 sPB[NL][16];
    __shared__ float2 sC[NL][256];
    __shared__ float2 sD[4][256];
    __shared__ float2 sE[2][256];
    __shared__ float2 sU[256];
    __shared__ float  sG[256];
    __shared__ float  sA1[192], sA2[144];

    const int t = threadIdx.x;

    if (t < NL * NQ) {
        float phi = w[t * 3 + 0], th = w[t * 3 + 1], om = w[t * 3 + 2];
        float st, ct; __sincosf(0.5f * th, &st, &ct);
        float a = 0.5f * (phi + om), b = 0.5f * (phi - om);
        float sa, ca, sb, cb;
        __sincosf(a, &sa, &ca);
        __sincosf(b, &sb, &cb);
        sGate[t][0] = make_float2(ca * ct, -sa * ct);
        sGate[t][1] = make_float2(-cb * st, -sb * st);
        sGate[t][2] = make_float2(cb * st, -sb * st);
        sGate[t][3] = make_float2(ca * ct, sa * ct);
    }
    __syncthreads();

    {
        int l = t >> 5, r = t & 31;
        int which = r >> 4, idx = r & 15;
        int i = idx >> 2, j = idx & 3;
        const float2* gA = sGate[l * 4 + which * 2 + 0];
        const float2* gB = sGate[l * 4 + which * 2 + 1];
        float2 v = cmul(gA[(i >> 1) * 2 + (j >> 1)], gB[(i & 1) * 2 + (j & 1)]);
        if (which) sPB[l][idx] = v; else sPA[l][idx] = v;
    }
    __syncthreads();

    // C_l[sigma(m)][n] = PA[m>>2][n>>2]*PB[m&3][n&3]; sigma = CNOT ring.
    {
        int l = t >> 5, r = t & 31;
#pragma unroll
        for (int j = 0; j < 8; j++) {
            int idx = r + 32 * j;
            int m = idx >> 4, nn = idx & 15;
            int mp = m;
            mp = cnot_map(mp, 0, 1);
            mp = cnot_map(mp, 1, 2);
            mp = cnot_map(mp, 2, 3);
            mp = cnot_map(mp, 3, 0);
            float2 v = cmul(sPA[l][(m >> 2) * 4 + (nn >> 2)],
                            sPB[l][(m & 3) * 4 + (nn & 3)]);
            sC[l][mp * 16 + nn] = v;
        }
    }
    __syncthreads();

    // product tree: U = C7 C6 ... C0
    {
        int p = t >> 6, r = t & 63;
#pragma unroll
        for (int j = 0; j < 4; j++) {
            int idx = r + 64 * j;
            int i = idx >> 4, col = idx & 15;
            float2 acc = make_float2(0.0f, 0.0f);
#pragma unroll
            for (int k = 0; k < 16; k++)
                acc = cfma(sC[2 * p + 1][i * 16 + k], sC[2 * p][k * 16 + col], acc);
            sD[p][idx] = acc;
        }
    }
    __syncthreads();
    {
        int qq = t >> 7, r = t & 127;
#pragma unroll
        for (int j = 0; j < 2; j++) {
            int idx = r + 128 * j;
            int i = idx >> 4, col = idx & 15;
            float2 acc = make_float2(0.0f, 0.0f);
#pragma unroll
            for (int k = 0; k < 16; k++)
                acc = cfma(sD[2 * qq + 1][i * 16 + k], sD[2 * qq][k * 16 + col], acc);
            sE[qq][idx] = acc;
        }
    }
    __syncthreads();
    {
        int i = t >> 4, col = t & 15;
        float2 acc = make_float2(0.0f, 0.0f);
#pragma unroll
        for (int k = 0; k < 16; k++)
            acc = cfma(sE[1][i * 16 + k], sE[0][k * 16 + col], acc);
        sU[t] = acc;
    }
    __syncthreads();

    // H = U^dag Z0 U -> phase-folded real G
    {
        int j = t >> 4, k = t & 15;
        float hr = 0.0f, hi = 0.0f;
#pragma unroll
        for (int mm = 0; mm < 16; mm++) {
            float zz = ((mm >> 3) & 1) ? -1.0f : 1.0f;
            float2 uj = sU[mm * 16 + j], uk = sU[mm * 16 + k];
            hr += zz * (uj.x * uk.x + uj.y * uk.y);
            hi += zz * (uj.x * uk.y - uj.y * uk.x);
        }
        int q = (__popc(j) - __popc(k)) & 3;
        float gval = (q == 0) ? hr : (q == 1) ? -hi : (q == 2) ? -hr : hi;
        int gidx = 0;
#pragma unroll
        for (int wq = 0; wq < 4; wq++) {
            int bi = 3 - wq;
            int p = ((j >> bi) & 1) * 2 + ((k >> bi) & 1);
            gidx = gidx * 4 + p;
        }
        sG[gidx] = gval;
    }
    __syncthreads();

    const float V[4][3] = {{0.5f, 0.5f, 0.0f},
                           {0.0f, 0.0f, 0.5f},
                           {0.0f, 0.0f, 0.5f},
                           {0.5f, -0.5f, 0.0f}};
    if (t < 192) {
        int d = t % 3, p2 = (t / 3) & 3, p1 = (t / 12) & 3, p0 = t / 48;
        float acc = 0.0f;
#pragma unroll
        for (int p3 = 0; p3 < 4; p3++)
            acc += sG[((p0 * 4 + p1) * 4 + p2) * 4 + p3] * V[p3][d];
        sA1[t] = acc;
    }
    __syncthreads();
    if (t < 144) {
        int d = t % 3, c = (t / 3) % 3, rest = t / 9;
        int p1 = rest & 3, p0 = rest >> 2;
        float acc = 0.0f;
#pragma unroll
        for (int p2 = 0; p2 < 4; p2++)
            acc += sA1[((p0 * 4 + p1) * 4 + p2) * 3 + d] * V[p2][c];
        sA2[t] = acc;
    }
    __syncthreads();
    if (t < 108) {
        int d = t % 3, c = (t / 3) % 3, b = (t / 9) % 3, p0 = t / 27;
        float acc = 0.0f;
#pragma unroll
        for (int p1 = 0; p1 < 4; p1++)
            acc += sA2[((p0 * 4 + p1) * 3 + c) * 3 + d] * V[p1][b];
        sA1[t] = acc;
    }
    __syncthreads();
    if (t < 81) {
        int d = t % 3, c = (t / 3) % 3, b = (t / 9) % 3, a = t / 27;
        float acc = 0.0f;
#pragma unroll
        for (int p0 = 0; p0 < 4; p0++)
            acc += sA1[((p0 * 3 + b) * 3 + c) * 3 + d] * V[p0][a];
        g_T[(a * 9 + b * 3 + c) * 4 + d] = acc;
    } else if (t < 108) {
        g_T[(t - 81) * 4 + 3] = 0.0f;
    }

    __threadfence();
    __syncthreads();
    if (t == 0) cudaTriggerProgrammaticLaunchCompletion();
}

// ---- main building blocks ----
// Trig for 4 strided samples (i0 + 32k).
template <bool GUARD>
__device__ __forceinline__ void trig4(const float4* __restrict__ x, int n, int i0,
                                      float* c0, float* s0, float* c1, float* s1,
                                      float* c2, float* s2, float* c3, float* s3) {
#pragma unroll
    for (int k = 0; k < 4; k++) {
        int i = i0 + 32 * k;
        float4 v = (!GUARD || i < n) ? x[i] : make_float4(0.f, 0.f, 0.f, 0.f);
        __sincosf(v.x, &s0[k], &c0[k]);
        __sincosf(v.y, &s1[k], &c1[k]);
        __sincosf(v.z, &s2[k], &c2[k]);
        __sincosf(v.w, &s3[k], &c3[k]);
    }
}

// E-inline contraction for 4 strided samples (proven 64-reg form, R6).
template <bool GUARD>
__device__ __forceinline__ void contract4(const float4* __restrict__ sT,
                                          float* __restrict__ out, int n, int i0,
                                          const float* c0, const float* s0,
                                          const float* c1, const float* s1,
                                          const float* c2, const float* s2,
                                          const float* c3, const float* s3) {
    float E[4];
#pragma unroll
    for (int u = 0; u < 9; u++) {
        const float4 t0 = sT[u * 3 + 0];
        const float4 t1 = sT[u * 3 + 1];
        const float4 t2 = sT[u * 3 + 2];
        const int a = u / 3, b = u % 3;  // compile-time under unroll
#pragma unroll
        for (int k = 0; k < 4; k++) {
            float a0 = fmaf(t0.z, s3[k], fmaf(t0.y, c3[k], t0.x));
            float a1 = fmaf(t1.z, s3[k], fmaf(t1.y, c3[k], t1.x));
            float a2 = fmaf(t2.z, s3[k], fmaf(t2.y, c3[k], t2.x));
            float r  = fmaf(a2, s2[k], fmaf(a1, c2[k], a0));
            if (a == 0 && b == 0) {
                E[k] = r;
            } else if (a == 0) {
                E[k] = fmaf(r, (b == 1) ? c1[k] : s1[k], E[k]);
            } else if (b == 0) {
                E[k] = fmaf(r, (a == 1) ? c0[k] : s0[k], E[k]);
            } else {
                float f0v = (a == 1) ? c0[k] : s0[k];
                float f1v = (b == 1) ? c1[k] : s1[k];
                E[k] = fmaf(r * f0v, f1v, E[k]);
            }
        }
    }
#pragma unroll
    for (int k = 0; k < 4; k++) {
        int i = i0 + 32 * k;
        if (!GUARD || i < n) out[i] = E[k];
    }
}

// Main: each warp owns TWO consecutive 128-sample tiles, run as two
// hardcoded sequential halves (registers reused; no stride loop). Grid = 512
// blocks <= 592 slots at 4 CTA/SM -> single resident round, no ragged drain.
// Half A's trig runs pre-sync to overlap setup via PDL.
__global__ void __launch_bounds__(256, 4) vqc_main(const float4* __restrict__ x,
                                                   float* __restrict__ out, int n) {
    __shared__ __align__(16) float4 sT[28];
    const int t = threadIdx.x;
    const int warp = t >> 5, lane = t & 31;
    const int regionBase = (blockIdx.x * 8 + warp) * 256;  // 2 tiles per warp
    const int iA = regionBase + lane;
    const int iB = regionBase + 128 + lane;
    const bool anyA = (regionBase < n);
    const bool anyB = (regionBase + 128 < n);
    const bool fullRegion = (regionBase + 255 < n);

    float c0[4], s0[4], c1[4], s1[4], c2[4], s2[4], c3[4], s3[4];

    // ---- half A trig: overlaps setup via PDL ----
    if (fullRegion) {
        trig4<false>(x, n, iA, c0, s0, c1, s1, c2, s2, c3, s3);
    } else if (anyA) {
        trig4<true>(x, n, iA, c0, s0, c1, s1, c2, s2, c3, s3);
    }

    cudaGridDependencySynchronize();
    if (t < 28) sT[t] = reinterpret_cast<const float4*>(g_T)[t];
    __syncthreads();

    if (!anyA) return;

    if (fullRegion) {
        contract4<false>(sT, out, n, iA, c0, s0, c1, s1, c2, s2, c3, s3);
        trig4<false>(x, n, iB, c0, s0, c1, s1, c2, s2, c3, s3);
        contract4<false>(sT, out, n, iB, c0, s0, c1, s1, c2, s2, c3, s3);
    } else {
        contract4<true>(sT, out, n, iA, c0, s0, c1, s1, c2, s2, c3, s3);
        if (anyB) {
            trig4<true>(x, n, iB, c0, s0, c1, s1, c2, s2, c3, s3);
            contract4<true>(sT, out, n, iB, c0, s0, c1, s1, c2, s2, c3, s3);
        }
    }
}

extern "C" void kernel_launch(void* const* d_in, const int* in_sizes, int n_in,
                              void* d_out, int out_size) {
    const float* x = (const float*)d_in[0];        // (B, 4)
    const float* w = (const float*)d_in[1];        // (8, 4, 3)
    float* out = (float*)d_out;                    // (B,)
    int n = out_size;                              // B

    vqc_setup<<<1, 256>>>(w);

    int blocks = (n + 2047) / 2048;                // 2048 samples per block

    cudaLaunchConfig_t cfg = {};
    cfg.gridDim = dim3((unsigned)blocks, 1, 1);
    cfg.blockDim = dim3(256, 1, 1);
    cfg.dynamicSmemBytes = 0;
    cfg.stream = 0;
    cudaLaunchAttribute attrs[1];
    attrs[0].id = cudaLaunchAttributeProgrammaticStreamSerialization;
    attrs[0].val.programmaticStreamSerializationAllowed = 1;
    cfg.attrs = attrs;
    cfg.numAttrs = 1;
    cudaLaunchKernelEx(&cfg, vqc_main, (const float4*)x, out, n);
}

// round 14
// speedup vs baseline: 1.6171x; 1.6171x over previous
#include <cuda_runtime.h>
#include <cstdint>

#define NQ 4
#define NL 8

__device__ __align__(16) float g_T[112];   // 27 x (d0,d1,d2,pad)

__device__ __forceinline__ float2 cmul(float2 a, float2 b) {
    return make_float2(fmaf(a.x, b.x, -a.y * b.y), fmaf(a.x, b.y, a.y * b.x));
}
__device__ __forceinline__ float2 cfma(float2 a, float2 b, float2 acc) {
    acc.x = fmaf(a.x, b.x, fmaf(-a.y, b.y, acc.x));
    acc.y = fmaf(a.x, b.y, fmaf(a.y, b.x, acc.y));
    return acc;
}
__device__ __forceinline__ int cnot_map(int m, int c, int t) {
    int bc = 3 - c, bt = 3 - t;
    if ((m >> bc) & 1) m ^= (1 << bt);
    return m;
}

// One block, 512 threads (R14: was 256 — halves per-thread work on the
// critical path, 4 warps/SMSP for latency hiding). Log-depth product tree;
// early PDL trigger once g_T is written.
__global__ void __launch_bounds__(512) vqc_setup(const float* __restrict__ w) {
    __shared__ float2 sGate[NL * NQ][4];
    __shared__ float2 sPA[NL][16];
    __shared__ float2 sPB[NL][16];
    __shared__ float2 sC[NL][256];
    __shared__ float2 sD[4][256];
    __shared__ float2 sE[2][256];
    __shared__ float2 sU[256];
    __shared__ float  sG[256];
    __shared__ float  sA1[192], sA2[144];

    const int t = threadIdx.x;

    // ---- phase 0: gate matrices (t<32) ----
    if (t < NL * NQ) {
        float phi = w[t * 3 + 0], th = w[t * 3 + 1], om = w[t * 3 + 2];
        float st, ct; __sincosf(0.5f * th, &st, &ct);
        float a = 0.5f * (phi + om), b = 0.5f * (phi - om);
        float sa, ca, sb, cb;
        __sincosf(a, &sa, &ca);
        __sincosf(b, &sb, &cb);
        sGate[t][0] = make_float2(ca * ct, -sa * ct);
        sGate[t][1] = make_float2(-cb * st, -sb * st);
        sGate[t][2] = make_float2(cb * st, -sb * st);
        sGate[t][3] = make_float2(ca * ct, sa * ct);
    }
    __syncthreads();

    // ---- phase 1: pair Kronecker factors (256 entries; t<256) ----
    if (t < 256) {
        int l = t >> 5, r = t & 31;
        int which = r >> 4, idx = r & 15;
        int i = idx >> 2, j = idx & 3;
        const float2* gA = sGate[l * 4 + which * 2 + 0];
        const float2* gB = sGate[l * 4 + which * 2 + 1];
        float2 v = cmul(gA[(i >> 1) * 2 + (j >> 1)], gB[(i & 1) * 2 + (j & 1)]);
        if (which) sPB[l][idx] = v; else sPA[l][idx] = v;
    }
    __syncthreads();

    // ---- phase 2: C_l[sigma(m)][n] = PA*PB (2048 entries; 4/thread) ----
    {
        int l = t >> 6, r = t & 63;
#pragma unroll
        for (int j = 0; j < 4; j++) {
            int idx = r + 64 * j;
            int m = idx >> 4, nn = idx & 15;
            int mp = m;
            mp = cnot_map(mp, 0, 1);
            mp = cnot_map(mp, 1, 2);
            mp = cnot_map(mp, 2, 3);
            mp = cnot_map(mp, 3, 0);
            float2 v = cmul(sPA[l][(m >> 2) * 4 + (nn >> 2)],
                            sPB[l][(m & 3) * 4 + (nn & 3)]);
            sC[l][mp * 16 + nn] = v;
        }
    }
    __syncthreads();

    // ---- phase 3: product tree. U = C7 C6 ... C0 ----
    // round 1: 4 matmuls, 1024 outputs, 2/thread
    {
        int p = t >> 7, r = t & 127;
#pragma unroll
        for (int j = 0; j < 2; j++) {
            int idx = r + 128 * j;
            int i = idx >> 4, col = idx & 15;
            float2 acc = make_float2(0.0f, 0.0f);
#pragma unroll
            for (int k = 0; k < 16; k++)
                acc = cfma(sC[2 * p + 1][i * 16 + k], sC[2 * p][k * 16 + col], acc);
            sD[p][idx] = acc;
        }
    }
    __syncthreads();
    // round 2: 2 matmuls, 512 outputs, 1/thread
    {
        int qq = t >> 8, idx = t & 255;
        int i = idx >> 4, col = idx & 15;
        float2 acc = make_float2(0.0f, 0.0f);
#pragma unroll
        for (int k = 0; k < 16; k++)
            acc = cfma(sD[2 * qq + 1][i * 16 + k], sD[2 * qq][k * 16 + col], acc);
        sE[qq][idx] = acc;
    }
    __syncthreads();
    // round 3: 256 outputs (t<256)
    if (t < 256) {
        int i = t >> 4, col = t & 15;
        float2 acc = make_float2(0.0f, 0.0f);
#pragma unroll
        for (int k = 0; k < 16; k++)
            acc = cfma(sE[1][i * 16 + k], sE[0][k * 16 + col], acc);
        sU[t] = acc;
    }
    __syncthreads();

    // ---- phase 4: H = U^dag Z0 U -> phase-folded real G (t<256) ----
    if (t < 256) {
        int j = t >> 4, k = t & 15;
        float hr = 0.0f, hi = 0.0f;
#pragma unroll
        for (int mm = 0; mm < 16; mm++) {
            float zz = ((mm >> 3) & 1) ? -1.0f : 1.0f;
            float2 uj = sU[mm * 16 + j], uk = sU[mm * 16 + k];
            hr += zz * (uj.x * uk.x + uj.y * uk.y);
            hi += zz * (uj.x * uk.y - uj.y * uk.x);
        }
        int q = (__popc(j) - __popc(k)) & 3;
        float gval = (q == 0) ? hr : (q == 1) ? -hi : (q == 2) ? -hr : hi;
        int gidx = 0;
#pragma unroll
        for (int wq = 0; wq < 4; wq++) {
            int bi = 3 - wq;
            int p = ((j >> bi) & 1) * 2 + ((k >> bi) & 1);
            gidx = gidx * 4 + p;
        }
        sG[gidx] = gval;
    }
    __syncthreads();

    // ---- phase 5: Tucker contract pair-codes (4) with V (4x3) ----
    const float V[4][3] = {{0.5f, 0.5f, 0.0f},
                           {0.0f, 0.0f, 0.5f},
                           {0.0f, 0.0f, 0.5f},
                           {0.5f, -0.5f, 0.0f}};
    if (t < 192) {
        int d = t % 3, p2 = (t / 3) & 3, p1 = (t / 12) & 3, p0 = t / 48;
        float acc = 0.0f;
#pragma unroll
        for (int p3 = 0; p3 < 4; p3++)
            acc += sG[((p0 * 4 + p1) * 4 + p2) * 4 + p3] * V[p3][d];
        sA1[t] = acc;
    }
    __syncthreads();
    if (t < 144) {
        int d = t % 3, c = (t / 3) % 3, rest = t / 9;
        int p1 = rest & 3, p0 = rest >> 2;
        float acc = 0.0f;
#pragma unroll
        for (int p2 = 0; p2 < 4; p2++)
            acc += sA1[((p0 * 4 + p1) * 4 + p2) * 3 + d] * V[p2][c];
        sA2[t] = acc;
    }
    __syncthreads();
    if (t < 108) {
        int d = t % 3, c = (t / 3) % 3, b = (t / 9) % 3, p0 = t / 27;
        float acc = 0.0f;
#pragma unroll
        for (int p1 = 0; p1 < 4; p1++)
            acc += sA2[((p0 * 4 + p1) * 3 + c) * 3 + d] * V[p1][b];
        sA1[t] = acc;
    }
    __syncthreads();
    if (t < 81) {
        int d = t % 3, c = (t / 3) % 3, b = (t / 9) % 3, a = t / 27;
        float acc = 0.0f;
#pragma unroll
        for (int p0 = 0; p0 < 4; p0++)
            acc += sA1[((p0 * 3 + b) * 3 + c) * 3 + d] * V[p0][a];
        g_T[(a * 9 + b * 3 + c) * 4 + d] = acc;
    } else if (t < 108) {
        g_T[(t - 81) * 4 + 3] = 0.0f;
    }

    // Early release of the PDL-dependent main kernel: g_T is final here.
    __threadfence();
    __syncthreads();
    if (t == 0) cudaTriggerProgrammaticLaunchCompletion();
}

// Contraction: r9-array body (R3/R12's fastest-measured form), strided
// coalesced indices i0 + 32k. Template GUARD compiles out bounds checks.
template <bool GUARD>
__device__ __forceinline__ void run_tile(float* __restrict__ out, int n,
                                         const float4* __restrict__ sT, int i0,
                                         const float* c0, const float* s0,
                                         const float* c1, const float* s1,
                                         const float* c2, const float* s2,
                                         const float* c3, const float* s3) {
    float r9[4][9];
#pragma unroll
    for (int u = 0; u < 9; u++) {
        const float4 t0 = sT[u * 3 + 0];
        const float4 t1 = sT[u * 3 + 1];
        const float4 t2 = sT[u * 3 + 2];
#pragma unroll
        for (int k = 0; k < 4; k++) {
            float a0 = fmaf(t0.z, s3[k], fmaf(t0.y, c3[k], t0.x));
            float a1 = fmaf(t1.z, s3[k], fmaf(t1.y, c3[k], t1.x));
            float a2 = fmaf(t2.z, s3[k], fmaf(t2.y, c3[k], t2.x));
            r9[k][u] = fmaf(a2, s2[k], fmaf(a1, c2[k], a0));
        }
    }
#pragma unroll
    for (int k = 0; k < 4; k++) {
        float b0 = fmaf(r9[k][2], s1[k], fmaf(r9[k][1], c1[k], r9[k][0]));
        float b1 = fmaf(r9[k][5], s1[k], fmaf(r9[k][4], c1[k], r9[k][3]));
        float b2 = fmaf(r9[k][8], s1[k], fmaf(r9[k][7], c1[k], r9[k][6]));
        float E  = fmaf(b2, s0[k], fmaf(b1, c0[k], b0));
        int i = i0 + 32 * k;
        if (!GUARD || i < n) out[i] = E;
    }
}

// Main (R12 structure, unchanged — best measured): warp owns one 128-sample
// tile, all loads issued in the prologue before the PDL sync, exact grid.
__global__ void __launch_bounds__(256) vqc_main(const float4* __restrict__ x,
                                                float* __restrict__ out, int n) {
    __shared__ __align__(16) float4 sT[28];
    const int t = threadIdx.x;
    const int warp = t >> 5, lane = t & 31;
    const int tileBase = (blockIdx.x * 8 + warp) * 128;
    const int i0 = tileBase + lane;
    const bool active = (tileBase < n);
    const bool fullTile = (tileBase + 127 < n);

    // ---- T-independent prologue (overlaps setup via PDL) ----
    float c0[4], s0[4], c1[4], s1[4], c2[4], s2[4], c3[4], s3[4];
#pragma unroll
    for (int k = 0; k < 4; k++) {
        int i = i0 + 32 * k;
        float4 v = (active && (fullTile || i < n)) ? x[i]
                                                   : make_float4(0.f, 0.f, 0.f, 0.f);
        __sincosf(v.x, &s0[k], &c0[k]);
        __sincosf(v.y, &s1[k], &c1[k]);
        __sincosf(v.z, &s2[k], &c2[k]);
        __sincosf(v.w, &s3[k], &c3[k]);
    }

    // ---- wait for setup's early trigger, stage T ----
    cudaGridDependencySynchronize();
    if (t < 28) sT[t] = reinterpret_cast<const float4*>(g_T)[t];
    __syncthreads();

    if (!active) return;
    if (fullTile) {
        run_tile<false>(out, n, sT, i0, c0, s0, c1, s1, c2, s2, c3, s3);
    } else {
        run_tile<true>(out, n, sT, i0, c0, s0, c1, s1, c2, s2, c3, s3);
    }
}

extern "C" void kernel_launch(void* const* d_in, const int* in_sizes, int n_in,
                              void* d_out, int out_size) {
    const float* x = (const float*)d_in[0];        // (B, 4)
    const float* w = (const float*)d_in[1];        // (8, 4, 3)
    float* out = (float*)d_out;                    // (B,)
    int n = out_size;                              // B

    vqc_setup<<<1, 512>>>(w);

    int ntiles = (n + 127) / 128;
    int blocks = (ntiles + 7) / 8;                 // one tile per warp, exact

    cudaLaunchConfig_t cfg = {};
    cfg.gridDim = dim3((unsigned)blocks, 1, 1);
    cfg.blockDim = dim3(256, 1, 1);
    cfg.dynamicSmemBytes = 0;
    cfg.stream = 0;
    cudaLaunchAttribute attrs[1];
    attrs[0].id = cudaLaunchAttributeProgrammaticStreamSerialization;
    attrs[0].val.programmaticStreamSerializationAllowed = 1;
    cfg.attrs = attrs;
    cfg.numAttrs = 1;
    cudaLaunchKernelEx(&cfg, vqc_main, (const float4*)x, out, n);
}

// round 15
// speedup vs baseline: 1.7644x; 1.0911x over previous
#include <cuda_runtime.h>
#include <cstdint>

#define NQ 4
#define NL 8

__device__ __align__(16) float g_T[112];   // 27 x (d0,d1,d2,pad)

__device__ __forceinline__ float2 cmul(float2 a, float2 b) {
    return make_float2(fmaf(a.x, b.x, -a.y * b.y), fmaf(a.x, b.y, a.y * b.x));
}
__device__ __forceinline__ float2 cfma(float2 a, float2 b, float2 acc) {
    acc.x = fmaf(a.x, b.x, fmaf(-a.y, b.y, acc.x));
    acc.y = fmaf(a.x, b.y, fmaf(a.y, b.x, acc.y));
    return acc;
}
__device__ __forceinline__ int cnot_map(int m, int c, int t) {
    int bc = 3 - c, bt = 3 - t;
    if ((m >> bc) & 1) m ^= (1 << bt);
    return m;
}

// One block, 256 threads. R15: shortened critical path — C built directly
// from gates (no PA/PB stage), Tucker in 2 stages (pair contractions).
// 8 barriers total. Early PDL trigger once g_T is written.
__global__ void __launch_bounds__(256) vqc_setup(const float* __restrict__ w) {
    __shared__ float2 sGate[NL * NQ][4];
    __shared__ float2 sC[NL][256];
    __shared__ float2 sD[4][256];
    __shared__ float2 sE[2][256];
    __shared__ float2 sU[256];
    __shared__ float  sG[256];
    __shared__ float  sA[144];

    const int t = threadIdx.x;

    // ---- phase 0: gate matrices (t<32) ----
    if (t < NL * NQ) {
        float phi = w[t * 3 + 0], th = w[t * 3 + 1], om = w[t * 3 + 2];
        float st, ct; __sincosf(0.5f * th, &st, &ct);
        float a = 0.5f * (phi + om), b = 0.5f * (phi - om);
        float sa, ca, sb, cb;
        __sincosf(a, &sa, &ca);
        __sincosf(b, &sb, &cb);
        sGate[t][0] = make_float2(ca * ct, -sa * ct);
        sGate[t][1] = make_float2(-cb * st, -sb * st);
        sGate[t][2] = make_float2(cb * st, -sb * st);
        sGate[t][3] = make_float2(ca * ct, sa * ct);
    }
    __syncthreads();

    // ---- phase 1: C_l[sigma(m)][n] = prod_w g_w[m_w][n_w], direct ----
    // wire w <-> bit (3-w); sigma = CNOT ring applied c01,c12,c23,c30.
    {
        int l = t >> 5, r = t & 31;
        const float2* g0 = sGate[l * 4 + 0];
        const float2* g1 = sGate[l * 4 + 1];
        const float2* g2 = sGate[l * 4 + 2];
        const float2* g3 = sGate[l * 4 + 3];
#pragma unroll
        for (int j = 0; j < 8; j++) {
            int idx = r + 32 * j;
            int m = idx >> 4, nn = idx & 15;
            int mp = m;
            mp = cnot_map(mp, 0, 1);
            mp = cnot_map(mp, 1, 2);
            mp = cnot_map(mp, 2, 3);
            mp = cnot_map(mp, 3, 0);
            float2 v01 = cmul(g0[((m >> 3) & 1) * 2 + ((nn >> 3) & 1)],
                              g1[((m >> 2) & 1) * 2 + ((nn >> 2) & 1)]);
            float2 v23 = cmul(g2[((m >> 1) & 1) * 2 + ((nn >> 1) & 1)],
                              g3[(m & 1) * 2 + (nn & 1)]);
            sC[l][mp * 16 + nn] = cmul(v01, v23);
        }
    }
    __syncthreads();

    // ---- phase 2-4: product tree. U = C7 C6 ... C0 ----
    {
        int p = t >> 6, r = t & 63;
#pragma unroll
        for (int j = 0; j < 4; j++) {
            int idx = r + 64 * j;
            int i = idx >> 4, col = idx & 15;
            float2 acc = make_float2(0.0f, 0.0f);
#pragma unroll
            for (int k = 0; k < 16; k++)
                acc = cfma(sC[2 * p + 1][i * 16 + k], sC[2 * p][k * 16 + col], acc);
            sD[p][idx] = acc;
        }
    }
    __syncthreads();
    {
        int qq = t >> 7, r = t & 127;
#pragma unroll
        for (int j = 0; j < 2; j++) {
            int idx = r + 128 * j;
            int i = idx >> 4, col = idx & 15;
            float2 acc = make_float2(0.0f, 0.0f);
#pragma unroll
            for (int k = 0; k < 16; k++)
                acc = cfma(sD[2 * qq + 1][i * 16 + k], sD[2 * qq][k * 16 + col], acc);
            sE[qq][idx] = acc;
        }
    }
    __syncthreads();
    {
        int i = t >> 4, col = t & 15;
        float2 acc = make_float2(0.0f, 0.0f);
#pragma unroll
        for (int k = 0; k < 16; k++)
            acc = cfma(sE[1][i * 16 + k], sE[0][k * 16 + col], acc);
        sU[t] = acc;   // row-major (row i, col)
    }
    __syncthreads();

    // ---- phase 5: H = U^dag Z0 U -> phase-folded real G ----
    {
        int j = t >> 4, k = t & 15;
        float hr = 0.0f, hi = 0.0f;
#pragma unroll
        for (int mm = 0; mm < 16; mm++) {
            float zz = ((mm >> 3) & 1) ? -1.0f : 1.0f;
            float2 uj = sU[mm * 16 + j], uk = sU[mm * 16 + k];
            hr += zz * (uj.x * uk.x + uj.y * uk.y);
            hi += zz * (uj.x * uk.y - uj.y * uk.x);
        }
        int q = (__popc(j) - __popc(k)) & 3;
        float gval = (q == 0) ? hr : (q == 1) ? -hi : (q == 2) ? -hr : hi;
        int gidx = 0;
#pragma unroll
        for (int wq = 0; wq < 4; wq++) {
            int bi = 3 - wq;
            int p = ((j >> bi) & 1) * 2 + ((k >> bi) & 1);
            gidx = gidx * 4 + p;
        }
        sG[gidx] = gval;
    }
    __syncthreads();

    // ---- phase 6: Tucker stage A — contract (p2,p3) -> (c,d) ----
    // pair code 0:(0,0)->c^2, 1:(0,1)->cs, 2:(1,0)->cs, 3:(1,1)->s^2
    const float V[4][3] = {{0.5f, 0.5f, 0.0f},
                           {0.0f, 0.0f, 0.5f},
                           {0.0f, 0.0f, 0.5f},
                           {0.5f, -0.5f, 0.0f}};
    if (t < 144) {  // output [q01][c*3+d], q01 = p0*4+p1
        int cd = t % 9, q01 = t / 9;
        int c = cd / 3, d = cd % 3;
        float acc = 0.0f;
#pragma unroll
        for (int p2 = 0; p2 < 4; p2++) {
#pragma unroll
            for (int p3 = 0; p3 < 4; p3++)
                acc += sG[q01 * 16 + p2 * 4 + p3] * (V[p2][c] * V[p3][d]);
        }
        sA[q01 * 9 + cd] = acc;
    }
    __syncthreads();

    // ---- phase 7: Tucker stage B — contract (p0,p1) -> (a,b), write g_T ----
    if (t < 81) {
        int d = t % 3, c = (t / 3) % 3, b = (t / 9) % 3, a = t / 27;
        float acc = 0.0f;
#pragma unroll
        for (int p0 = 0; p0 < 4; p0++) {
#pragma unroll
            for (int p1 = 0; p1 < 4; p1++)
                acc += sA[(p0 * 4 + p1) * 9 + c * 3 + d] * (V[p0][a] * V[p1][b]);
        }
        g_T[(a * 9 + b * 3 + c) * 4 + d] = acc;
    } else if (t < 108) {
        g_T[(t - 81) * 4 + 3] = 0.0f;  // pad lanes
    }

    // Early release of the PDL-dependent main kernel: g_T is final here.
    __threadfence();
    __syncthreads();
    if (t == 0) cudaTriggerProgrammaticLaunchCompletion();
}

// Contraction: r9-array body (R12, best measured), strided coalesced indices
// i0 + 32k. Template GUARD compiles out bounds checks on full tiles.
template <bool GUARD>
__device__ __forceinline__ void run_tile(float* __restrict__ out, int n,
                                         const float4* __restrict__ sT, int i0,
                                         const float* c0, const float* s0,
                                         const float* c1, const float* s1,
                                         const float* c2, const float* s2,
                                         const float* c3, const float* s3) {
    float r9[4][9];
#pragma unroll
    for (int u = 0; u < 9; u++) {
        const float4 t0 = sT[u * 3 + 0];
        const float4 t1 = sT[u * 3 + 1];
        const float4 t2 = sT[u * 3 + 2];
#pragma unroll
        for (int k = 0; k < 4; k++) {
            float a0 = fmaf(t0.z, s3[k], fmaf(t0.y, c3[k], t0.x));
            float a1 = fmaf(t1.z, s3[k], fmaf(t1.y, c3[k], t1.x));
            float a2 = fmaf(t2.z, s3[k], fmaf(t2.y, c3[k], t2.x));
            r9[k][u] = fmaf(a2, s2[k], fmaf(a1, c2[k], a0));
        }
    }
#pragma unroll
    for (int k = 0; k < 4; k++) {
        float b0 = fmaf(r9[k][2], s1[k], fmaf(r9[k][1], c1[k], r9[k][0]));
        float b1 = fmaf(r9[k][5], s1[k], fmaf(r9[k][4], c1[k], r9[k][3]));
        float b2 = fmaf(r9[k][8], s1[k], fmaf(r9[k][7], c1[k], r9[k][6]));
        float E  = fmaf(b2, s0[k], fmaf(b1, c0[k], b0));
        int i = i0 + 32 * k;
        if (!GUARD || i < n) out[i] = E;
    }
}

// Main (R12 structure, unchanged — best measured): warp owns one 128-sample
// tile, all loads issued in the prologue before the PDL sync, exact grid.
__global__ void __launch_bounds__(256) vqc_main(const float4* __restrict__ x,
                                                float* __restrict__ out, int n) {
    __shared__ __align__(16) float4 sT[28];
    const int t = threadIdx.x;
    const int warp = t >> 5, lane = t & 31;
    const int tileBase = (blockIdx.x * 8 + warp) * 128;
    const int i0 = tileBase + lane;
    const bool active = (tileBase < n);
    const bool fullTile = (tileBase + 127 < n);

    // ---- T-independent prologue (overlaps setup via PDL) ----
    float c0[4], s0[4], c1[4], s1[4], c2[4], s2[4], c3[4], s3[4];
#pragma unroll
    for (int k = 0; k < 4; k++) {
        int i = i0 + 32 * k;
        float4 v = (active && (fullTile || i < n)) ? x[i]
                                                   : make_float4(0.f, 0.f, 0.f, 0.f);
        __sincosf(v.x, &s0[k], &c0[k]);
        __sincosf(v.y, &s1[k], &c1[k]);
        __sincosf(v.z, &s2[k], &c2[k]);
        __sincosf(v.w, &s3[k], &c3[k]);
    }

    // ---- wait for setup's early trigger, stage T ----
    cudaGridDependencySynchronize();
    if (t < 28) sT[t] = reinterpret_cast<const float4*>(g_T)[t];
    __syncthreads();

    if (!active) return;
    if (fullTile) {
        run_tile<false>(out, n, sT, i0, c0, s0, c1, s1, c2, s2, c3, s3);
    } else {
        run_tile<true>(out, n, sT, i0, c0, s0, c1, s1, c2, s2, c3, s3);
    }
}

extern "C" void kernel_launch(void* const* d_in, const int* in_sizes, int n_in,
                              void* d_out, int out_size) {
    const float* x = (const float*)d_in[0];        // (B, 4)
    const float* w = (const float*)d_in[1];        // (8, 4, 3)
    float* out = (float*)d_out;                    // (B,)
    int n = out_size;                              // B

    vqc_setup<<<1, 256>>>(w);

    int ntiles = (n + 127) / 128;
    int blocks = (ntiles + 7) / 8;                 // one tile per warp, exact

    cudaLaunchConfig_t cfg = {};
    cfg.gridDim = dim3((unsigned)blocks, 1, 1);
    cfg.blockDim = dim3(256, 1, 1);
    cfg.dynamicSmemBytes = 0;
    cfg.stream = 0;
    cudaLaunchAttribute attrs[1];
    attrs[0].id = cudaLaunchAttributeProgrammaticStreamSerialization;
    attrs[0].val.programmaticStreamSerializationAllowed = 1;
    cfg.attrs = attrs;
    cfg.numAttrs = 1;
    cudaLaunchKernelEx(&cfg, vqc_main, (const float4*)x, out, n);
}